// round 1
// baseline (speedup 1.0000x reference)
#include <cuda_runtime.h>
#include <cuda_bf16.h>
#include <cstdint>

#define BB 2
#define HH 8
#define DH 64
#define DM 512
#define NQ 4096
#define NK 4096

// -------- scratch (no allocations allowed) --------
__device__ float g_qh[BB*HH*NQ*DH];
__device__ float g_kh[BB*HH*NK*DH];
__device__ float g_vh[BB*HH*NK*DH];
__device__ float g_o [BB*HH*NQ*DH];

__device__ __forceinline__ float to_tf32(float x) {
    float r;
    asm("cvt.rna.tf32.f32 %0, %1;" : "=f"(r) : "f"(x));
    return r;
}

// D += A(16x8) * B(8x8), tf32 inputs, fp32 accum
__device__ __forceinline__ void mma8(float* d, const float* a, const float* b) {
    asm("mma.sync.aligned.m16n8k8.row.col.f32.tf32.tf32.f32 "
        "{%0,%1,%2,%3}, {%4,%5,%6,%7}, {%8,%9}, {%0,%1,%2,%3};"
        : "+f"(d[0]), "+f"(d[1]), "+f"(d[2]), "+f"(d[3])
        : "r"(__float_as_uint(a[0])), "r"(__float_as_uint(a[1])),
          "r"(__float_as_uint(a[2])), "r"(__float_as_uint(a[3])),
          "r"(__float_as_uint(b[0])), "r"(__float_as_uint(b[1])));
}

// ============================================================
// QKV projection: Y[b,h,n,d] = X[row] @ W^T + bias, scattered head-major.
// Block tile 128(M) x 64(N==one head). 8 warps = 4(m) x 2(n), warp tile 32x32.
// ============================================================
__global__ __launch_bounds__(256) void proj_head_kernel(
    const float* __restrict__ X, const float* __restrict__ W,
    const float* __restrict__ bias, int sel)
{
    float* dst = sel == 0 ? g_qh : (sel == 1 ? g_kh : g_vh);
    __shared__ float As[128][36];
    __shared__ float Ws[64][36];
    int tid = threadIdx.x;
    int lane = tid & 31, warp = tid >> 5;
    int g = lane >> 2, t = lane & 3;
    int wm = warp >> 1, wn = warp & 1;
    int m0 = blockIdx.x * 128;
    int h  = blockIdx.y;

    float acc[2][4][4];
#pragma unroll
    for (int i = 0; i < 2; i++)
#pragma unroll
        for (int j = 0; j < 4; j++)
#pragma unroll
            for (int c = 0; c < 4; c++) acc[i][j][c] = 0.f;

    int rl = tid >> 3, cl = (tid & 7) * 4;
    for (int k0 = 0; k0 < DM; k0 += 32) {
#pragma unroll
        for (int i = 0; i < 4; i++) {
            int r = rl + i * 32;
            float4 v = *(const float4*)(X + (size_t)(m0 + r) * DM + k0 + cl);
            As[r][cl]   = to_tf32(v.x);
            As[r][cl+1] = to_tf32(v.y);
            As[r][cl+2] = to_tf32(v.z);
            As[r][cl+3] = to_tf32(v.w);
        }
#pragma unroll
        for (int i = 0; i < 2; i++) {
            int r = rl + i * 32;
            float4 v = *(const float4*)(W + (size_t)(h * 64 + r) * DM + k0 + cl);
            Ws[r][cl]   = to_tf32(v.x);
            Ws[r][cl+1] = to_tf32(v.y);
            Ws[r][cl+2] = to_tf32(v.z);
            Ws[r][cl+3] = to_tf32(v.w);
        }
        __syncthreads();
#pragma unroll
        for (int kk = 0; kk < 4; kk++) {
            float a[2][4];
#pragma unroll
            for (int mt = 0; mt < 2; mt++) {
                int rb = wm * 32 + mt * 16;
                a[mt][0] = As[rb + g][kk*8 + t];
                a[mt][1] = As[rb + 8 + g][kk*8 + t];
                a[mt][2] = As[rb + g][kk*8 + t + 4];
                a[mt][3] = As[rb + 8 + g][kk*8 + t + 4];
            }
            float bf[4][2];
#pragma unroll
            for (int nt = 0; nt < 4; nt++) {
                int nl = wn * 32 + nt * 8 + g;
                bf[nt][0] = Ws[nl][kk*8 + t];
                bf[nt][1] = Ws[nl][kk*8 + t + 4];
            }
#pragma unroll
            for (int mt = 0; mt < 2; mt++)
#pragma unroll
                for (int nt = 0; nt < 4; nt++)
                    mma8(acc[mt][nt], a[mt], bf[nt]);
        }
        __syncthreads();
    }
    // epilogue: scatter to [b,h,q,d]
#pragma unroll
    for (int mt = 0; mt < 2; mt++) {
        int r0 = m0 + wm * 32 + mt * 16 + g;
        int r1 = r0 + 8;
#pragma unroll
        for (int nt = 0; nt < 4; nt++) {
            int col = wn * 32 + nt * 8 + 2 * t;
            float b0v = bias[h * 64 + col], b1v = bias[h * 64 + col + 1];
            int b_ = r0 >> 12, q_ = r0 & 4095;
            float* p = dst + (size_t)((b_ * HH + h) * NQ + q_) * DH + col;
            p[0] = acc[mt][nt][0] + b0v;
            p[1] = acc[mt][nt][1] + b1v;
            b_ = r1 >> 12; q_ = r1 & 4095;
            p = dst + (size_t)((b_ * HH + h) * NQ + q_) * DH + col;
            p[0] = acc[mt][nt][2] + b0v;
            p[1] = acc[mt][nt][3] + b1v;
        }
    }
}

// ============================================================
// Output projection: output[row,n] = concat_heads(g_o)[row] @ Wo^T + bo
// ============================================================
__global__ __launch_bounds__(256) void proj_out_kernel(
    const float* __restrict__ W, const float* __restrict__ bias,
    float* __restrict__ Y)
{
    __shared__ float As[128][36];
    __shared__ float Ws[64][36];
    int tid = threadIdx.x;
    int lane = tid & 31, warp = tid >> 5;
    int g = lane >> 2, t = lane & 3;
    int wm = warp >> 1, wn = warp & 1;
    int m0 = blockIdx.x * 128;
    int n0 = blockIdx.y * 64;

    float acc[2][4][4];
#pragma unroll
    for (int i = 0; i < 2; i++)
#pragma unroll
        for (int j = 0; j < 4; j++)
#pragma unroll
            for (int c = 0; c < 4; c++) acc[i][j][c] = 0.f;

    int rl = tid >> 3, cl = (tid & 7) * 4;
    for (int k0 = 0; k0 < DM; k0 += 32) {
        int head = k0 >> 6;
        int dd = (k0 & 63) + cl;
#pragma unroll
        for (int i = 0; i < 4; i++) {
            int r = rl + i * 32;
            int row = m0 + r;
            int b_ = row >> 12, q_ = row & 4095;
            float4 v = *(const float4*)(g_o + (size_t)((b_ * HH + head) * NQ + q_) * DH + dd);
            As[r][cl]   = to_tf32(v.x);
            As[r][cl+1] = to_tf32(v.y);
            As[r][cl+2] = to_tf32(v.z);
            As[r][cl+3] = to_tf32(v.w);
        }
#pragma unroll
        for (int i = 0; i < 2; i++) {
            int r = rl + i * 32;
            float4 v = *(const float4*)(W + (size_t)(n0 + r) * DM + k0 + cl);
            Ws[r][cl]   = to_tf32(v.x);
            Ws[r][cl+1] = to_tf32(v.y);
            Ws[r][cl+2] = to_tf32(v.z);
            Ws[r][cl+3] = to_tf32(v.w);
        }
        __syncthreads();
#pragma unroll
        for (int kk = 0; kk < 4; kk++) {
            float a[2][4];
#pragma unroll
            for (int mt = 0; mt < 2; mt++) {
                int rb = wm * 32 + mt * 16;
                a[mt][0] = As[rb + g][kk*8 + t];
                a[mt][1] = As[rb + 8 + g][kk*8 + t];
                a[mt][2] = As[rb + g][kk*8 + t + 4];
                a[mt][3] = As[rb + 8 + g][kk*8 + t + 4];
            }
            float bf[4][2];
#pragma unroll
            for (int nt = 0; nt < 4; nt++) {
                int nl = wn * 32 + nt * 8 + g;
                bf[nt][0] = Ws[nl][kk*8 + t];
                bf[nt][1] = Ws[nl][kk*8 + t + 4];
            }
#pragma unroll
            for (int mt = 0; mt < 2; mt++)
#pragma unroll
                for (int nt = 0; nt < 4; nt++)
                    mma8(acc[mt][nt], a[mt], bf[nt]);
        }
        __syncthreads();
    }
#pragma unroll
    for (int mt = 0; mt < 2; mt++) {
        int r0 = m0 + wm * 32 + mt * 16 + g;
        int r1 = r0 + 8;
#pragma unroll
        for (int nt = 0; nt < 4; nt++) {
            int col = wn * 32 + nt * 8 + 2 * t;
            float b0v = bias[n0 + col], b1v = bias[n0 + col + 1];
            float* p = Y + (size_t)r0 * DM + n0 + col;
            p[0] = acc[mt][nt][0] + b0v;
            p[1] = acc[mt][nt][1] + b1v;
            p = Y + (size_t)r1 * DM + n0 + col;
            p[0] = acc[mt][nt][2] + b0v;
            p[1] = acc[mt][nt][3] + b1v;
        }
    }
}

// ============================================================
// Attention: per block = one (b,h) and one 64-row Q tile.
// Pass 1: Z = rowsum exp(S). Pass 2: recompute S, write P = exp/Z to gmem,
// O += P @ V. 8 warps: S as 2(m)x4(n) warp tiles of 32x32 over 64x128 S tile.
// ============================================================
#define SM_Q 0
#define SM_K 4352
#define SM_V 13056
#define SM_P 21760
#define SM_Z 30208
#define SM_M 30272
#define SMEM_BYTES 129280

__global__ __launch_bounds__(256) void attn_kernel(
    const unsigned char* __restrict__ mask, float* __restrict__ attn)
{
    extern __shared__ float sm[];
    float* Qs = sm + SM_Q;                               // [64][68]
    float* Ks = sm + SM_K;                               // [128][68]
    float* Vs = sm + SM_V;                               // [128][68]
    float* Ps = sm + SM_P;                               // [64][132]
    float* Zs = sm + SM_Z;                               // [64]
    unsigned int* Ms = (unsigned int*)(sm + SM_M);       // [64][32] words

    int tid = threadIdx.x;
    int lane = tid & 31, warp = tid >> 5;
    int g = lane >> 2, t = lane & 3;
    int wm = warp >> 2;   // 0..1 : S row half
    int wn = warp & 3;    // 0..3 : S col quarter / O k-chunk
    int q0 = blockIdx.x * 64;
    int bh = blockIdx.y;
    int b = bh >> 3, h = bh & 7;
    size_t headbase = (size_t)(b * HH + h) * NQ * DH;
    const unsigned char* mbase = mask + (size_t)(b * NQ + q0) * NK;

    // load Q tile (pre-scaled by 1/sqrt(d)=1/8)
#pragma unroll
    for (int j = 0; j < 4; j++) {
        int idx = tid + j * 256;
        int r = idx >> 4, c = (idx & 15) * 4;
        float4 v = *(const float4*)(g_qh + headbase + (size_t)(q0 + r) * DH + c);
        Qs[r*68 + c]   = to_tf32(v.x * 0.125f);
        Qs[r*68 + c+1] = to_tf32(v.y * 0.125f);
        Qs[r*68 + c+2] = to_tf32(v.z * 0.125f);
        Qs[r*68 + c+3] = to_tf32(v.w * 0.125f);
    }
    if (tid < 64) Zs[tid] = 0.f;

    // -------- pass 1: row sums Z --------
    for (int kt = 0; kt < NK / 128; kt++) {
        int k0 = kt * 128;
        __syncthreads();
#pragma unroll
        for (int j = 0; j < 8; j++) {
            int idx = tid + j * 256;
            int r = idx >> 4, c = (idx & 15) * 4;
            float4 v = *(const float4*)(g_kh + headbase + (size_t)(k0 + r) * DH + c);
            Ks[r*68 + c]   = to_tf32(v.x);
            Ks[r*68 + c+1] = to_tf32(v.y);
            Ks[r*68 + c+2] = to_tf32(v.z);
            Ks[r*68 + c+3] = to_tf32(v.w);
        }
#pragma unroll
        for (int j = 0; j < 8; j++) {
            int idx = tid + j * 256;
            int r = idx >> 5, c = idx & 31;
            Ms[r * 32 + c] = *(const unsigned int*)(mbase + (size_t)r * NK + k0 + c * 4);
        }
        __syncthreads();

        float sacc[2][4][4];
#pragma unroll
        for (int i = 0; i < 2; i++)
#pragma unroll
            for (int j = 0; j < 4; j++)
#pragma unroll
                for (int c = 0; c < 4; c++) sacc[i][j][c] = 0.f;
#pragma unroll
        for (int kk = 0; kk < 8; kk++) {
            float a[2][4];
#pragma unroll
            for (int mt = 0; mt < 2; mt++) {
                int rb = wm * 32 + mt * 16;
                a[mt][0] = Qs[(rb + g) * 68 + kk*8 + t];
                a[mt][1] = Qs[(rb + 8 + g) * 68 + kk*8 + t];
                a[mt][2] = Qs[(rb + g) * 68 + kk*8 + t + 4];
                a[mt][3] = Qs[(rb + 8 + g) * 68 + kk*8 + t + 4];
            }
            float bf[4][2];
#pragma unroll
            for (int nt = 0; nt < 4; nt++) {
                int nl = wn * 32 + nt * 8 + g;
                bf[nt][0] = Ks[nl * 68 + kk*8 + t];
                bf[nt][1] = Ks[nl * 68 + kk*8 + t + 4];
            }
#pragma unroll
            for (int mt = 0; mt < 2; mt++)
#pragma unroll
                for (int nt = 0; nt < 4; nt++)
                    mma8(sacc[mt][nt], a[mt], bf[nt]);
        }
        const unsigned char* Mb = (const unsigned char*)Ms;
        float rsum[4] = {0.f, 0.f, 0.f, 0.f};
#pragma unroll
        for (int mt = 0; mt < 2; mt++) {
            int r0 = wm * 32 + mt * 16 + g, r1 = r0 + 8;
#pragma unroll
            for (int nt = 0; nt < 4; nt++) {
                int c0 = wn * 32 + nt * 8 + 2 * t;
                float p00 = Mb[r0*128 + c0]     ? 0.f : __expf(sacc[mt][nt][0]);
                float p01 = Mb[r0*128 + c0 + 1] ? 0.f : __expf(sacc[mt][nt][1]);
                float p10 = Mb[r1*128 + c0]     ? 0.f : __expf(sacc[mt][nt][2]);
                float p11 = Mb[r1*128 + c0 + 1] ? 0.f : __expf(sacc[mt][nt][3]);
                rsum[mt*2]     += p00 + p01;
                rsum[mt*2 + 1] += p10 + p11;
            }
        }
#pragma unroll
        for (int i = 0; i < 4; i++) {
            rsum[i] += __shfl_xor_sync(0xffffffffu, rsum[i], 1);
            rsum[i] += __shfl_xor_sync(0xffffffffu, rsum[i], 2);
        }
        if (t == 0) {
            atomicAdd(&Zs[wm*32 + g],      rsum[0]);
            atomicAdd(&Zs[wm*32 + 8 + g],  rsum[1]);
            atomicAdd(&Zs[wm*32 + 16 + g], rsum[2]);
            atomicAdd(&Zs[wm*32 + 24 + g], rsum[3]);
        }
    }
    __syncthreads();
    if (tid < 64) Zs[tid] = 1.0f / Zs[tid];
    __syncthreads();
    float invz[4];
    invz[0] = Zs[wm*32 + g];
    invz[1] = Zs[wm*32 + 8 + g];
    invz[2] = Zs[wm*32 + 16 + g];
    invz[3] = Zs[wm*32 + 24 + g];

    float oacc[2][8][4];
#pragma unroll
    for (int i = 0; i < 2; i++)
#pragma unroll
        for (int j = 0; j < 8; j++)
#pragma unroll
            for (int c = 0; c < 4; c++) oacc[i][j][c] = 0.f;

    // -------- pass 2: write P, accumulate O --------
    for (int kt = 0; kt < NK / 128; kt++) {
        int k0 = kt * 128;
        __syncthreads();
#pragma unroll
        for (int j = 0; j < 8; j++) {
            int idx = tid + j * 256;
            int r = idx >> 4, c = (idx & 15) * 4;
            float4 v = *(const float4*)(g_kh + headbase + (size_t)(k0 + r) * DH + c);
            Ks[r*68 + c]   = to_tf32(v.x);
            Ks[r*68 + c+1] = to_tf32(v.y);
            Ks[r*68 + c+2] = to_tf32(v.z);
            Ks[r*68 + c+3] = to_tf32(v.w);
            float4 w = *(const float4*)(g_vh + headbase + (size_t)(k0 + r) * DH + c);
            Vs[r*68 + c]   = to_tf32(w.x);
            Vs[r*68 + c+1] = to_tf32(w.y);
            Vs[r*68 + c+2] = to_tf32(w.z);
            Vs[r*68 + c+3] = to_tf32(w.w);
        }
#pragma unroll
        for (int j = 0; j < 8; j++) {
            int idx = tid + j * 256;
            int r = idx >> 5, c = idx & 31;
            Ms[r * 32 + c] = *(const unsigned int*)(mbase + (size_t)r * NK + k0 + c * 4);
        }
        __syncthreads();

        float sacc[2][4][4];
#pragma unroll
        for (int i = 0; i < 2; i++)
#pragma unroll
            for (int j = 0; j < 4; j++)
#pragma unroll
                for (int c = 0; c < 4; c++) sacc[i][j][c] = 0.f;
#pragma unroll
        for (int kk = 0; kk < 8; kk++) {
            float a[2][4];
#pragma unroll
            for (int mt = 0; mt < 2; mt++) {
                int rb = wm * 32 + mt * 16;
                a[mt][0] = Qs[(rb + g) * 68 + kk*8 + t];
                a[mt][1] = Qs[(rb + 8 + g) * 68 + kk*8 + t];
                a[mt][2] = Qs[(rb + g) * 68 + kk*8 + t + 4];
                a[mt][3] = Qs[(rb + 8 + g) * 68 + kk*8 + t + 4];
            }
            float bf[4][2];
#pragma unroll
            for (int nt = 0; nt < 4; nt++) {
                int nl = wn * 32 + nt * 8 + g;
                bf[nt][0] = Ks[nl * 68 + kk*8 + t];
                bf[nt][1] = Ks[nl * 68 + kk*8 + t + 4];
            }
#pragma unroll
            for (int mt = 0; mt < 2; mt++)
#pragma unroll
                for (int nt = 0; nt < 4; nt++)
                    mma8(sacc[mt][nt], a[mt], bf[nt]);
        }
        const unsigned char* Mb = (const unsigned char*)Ms;
#pragma unroll
        for (int mt = 0; mt < 2; mt++) {
            int r0 = wm * 32 + mt * 16 + g, r1 = r0 + 8;
#pragma unroll
            for (int nt = 0; nt < 4; nt++) {
                int c0 = wn * 32 + nt * 8 + 2 * t;
                float p00 = Mb[r0*128 + c0]     ? 0.f : __expf(sacc[mt][nt][0]) * invz[mt*2];
                float p01 = Mb[r0*128 + c0 + 1] ? 0.f : __expf(sacc[mt][nt][1]) * invz[mt*2];
                float p10 = Mb[r1*128 + c0]     ? 0.f : __expf(sacc[mt][nt][2]) * invz[mt*2 + 1];
                float p11 = Mb[r1*128 + c0 + 1] ? 0.f : __expf(sacc[mt][nt][3]) * invz[mt*2 + 1];
                Ps[r0*132 + c0]     = p00;
                Ps[r0*132 + c0 + 1] = p01;
                Ps[r1*132 + c0]     = p10;
                Ps[r1*132 + c0 + 1] = p11;
            }
        }
        __syncthreads();
        // coalesced P -> gmem (attn layout [h*B+b, q, k])
        size_t abase = ((size_t)(h * BB + b) * NQ + q0) * NK + k0;
#pragma unroll
        for (int j = 0; j < 8; j++) {
            int idx = tid + j * 256;
            int r = idx >> 5, c = (idx & 31) * 4;
            float4 v = *(const float4*)(Ps + r * 132 + c);
            *(float4*)(attn + abase + (size_t)r * NK + c) = v;
        }
        // O += P @ V  (warp wn handles k-chunk wn*32..+32)
#pragma unroll
        for (int kk = 0; kk < 4; kk++) {
            int kb = wn * 32 + kk * 8;
            float a[2][4];
#pragma unroll
            for (int mt = 0; mt < 2; mt++) {
                int rb = wm * 32 + mt * 16;
                a[mt][0] = to_tf32(Ps[(rb + g) * 132 + kb + t]);
                a[mt][1] = to_tf32(Ps[(rb + 8 + g) * 132 + kb + t]);
                a[mt][2] = to_tf32(Ps[(rb + g) * 132 + kb + t + 4]);
                a[mt][3] = to_tf32(Ps[(rb + 8 + g) * 132 + kb + t + 4]);
            }
            float bf[8][2];
#pragma unroll
            for (int nt = 0; nt < 8; nt++) {
                bf[nt][0] = Vs[(kb + t) * 68 + nt * 8 + g];
                bf[nt][1] = Vs[(kb + t + 4) * 68 + nt * 8 + g];
            }
#pragma unroll
            for (int mt = 0; mt < 2; mt++)
#pragma unroll
                for (int nt = 0; nt < 8; nt++)
                    mma8(oacc[mt][nt], a[mt], bf[nt]);
        }
    }

    // reduce O across the 4 k-chunk warps via smem (reuse Ps as Os[64][68])
    __syncthreads();
    float* Os = Ps;
    for (int i = tid; i < 64 * 68; i += 256) Os[i] = 0.f;
    __syncthreads();
#pragma unroll
    for (int mt = 0; mt < 2; mt++) {
        int r0 = wm * 32 + mt * 16 + g, r1 = r0 + 8;
#pragma unroll
        for (int nt = 0; nt < 8; nt++) {
            int c0 = nt * 8 + 2 * t;
            atomicAdd(&Os[r0 * 68 + c0],     oacc[mt][nt][0]);
            atomicAdd(&Os[r0 * 68 + c0 + 1], oacc[mt][nt][1]);
            atomicAdd(&Os[r1 * 68 + c0],     oacc[mt][nt][2]);
            atomicAdd(&Os[r1 * 68 + c0 + 1], oacc[mt][nt][3]);
        }
    }
    __syncthreads();
#pragma unroll
    for (int j = 0; j < 4; j++) {
        int idx = tid + j * 256;
        int r = idx >> 4, c = (idx & 15) * 4;
        float4 v;
        v.x = Os[r * 68 + c];
        v.y = Os[r * 68 + c + 1];
        v.z = Os[r * 68 + c + 2];
        v.w = Os[r * 68 + c + 3];
        *(float4*)(g_o + headbase + (size_t)(q0 + r) * DH + c) = v;
    }
}

// ============================================================
extern "C" void kernel_launch(void* const* d_in, const int* in_sizes, int n_in,
                              void* d_out, int out_size)
{
    const float* q  = (const float*)d_in[0];
    const float* k  = (const float*)d_in[1];
    const float* v  = (const float*)d_in[2];
    const unsigned char* mask = (const unsigned char*)d_in[3];
    const float* Wq = (const float*)d_in[4];
    const float* bq = (const float*)d_in[5];
    const float* Wk = (const float*)d_in[6];
    const float* bk = (const float*)d_in[7];
    const float* Wv = (const float*)d_in[8];
    const float* bv = (const float*)d_in[9];
    const float* Wo = (const float*)d_in[10];
    const float* bo = (const float*)d_in[11];

    float* out  = (float*)d_out;
    float* attn = out;                                    // [16, 4096, 4096]
    float* outp = out + (size_t)HH * BB * NQ * NK;        // [2, 4096, 512]

    dim3 blk(256);
    proj_head_kernel<<<dim3(64, 8), blk>>>(q, Wq, bq, 0);
    proj_head_kernel<<<dim3(64, 8), blk>>>(k, Wk, bk, 1);
    proj_head_kernel<<<dim3(64, 8), blk>>>(v, Wv, bv, 2);

    cudaFuncSetAttribute(attn_kernel, cudaFuncAttributeMaxDynamicSharedMemorySize, SMEM_BYTES);
    attn_kernel<<<dim3(NQ / 64, BB * HH), blk, SMEM_BYTES>>>(mask, attn);

    proj_out_kernel<<<dim3(64, 8), blk>>>(Wo, bo, outp);
}

// round 2
// speedup vs baseline: 1.1716x; 1.1716x over previous
#include <cuda_runtime.h>
#include <cuda_bf16.h>
#include <cstdint>

#define BB 2
#define HH 8
#define DH 64
#define DM 512
#define NQ 4096
#define NK 4096

// -------- scratch (no allocations allowed) --------
__device__ float g_qh[BB*HH*NQ*DH];
__device__ float g_kh[BB*HH*NK*DH];
__device__ float g_vh[BB*HH*NK*DH];
__device__ float g_o [BB*HH*NQ*DH];   // UNNORMALIZED O (E @ V)
__device__ float g_zi[BB*HH*NQ];      // 1 / rowsum(exp(S))

__device__ __forceinline__ float to_tf32(float x) {
    float r;
    asm("cvt.rna.tf32.f32 %0, %1;" : "=f"(r) : "f"(x));
    return r;
}

// D += A(16x8) * B(8x8), tf32 inputs, fp32 accum
__device__ __forceinline__ void mma8(float* d, const float* a, const float* b) {
    asm("mma.sync.aligned.m16n8k8.row.col.f32.tf32.tf32.f32 "
        "{%0,%1,%2,%3}, {%4,%5,%6,%7}, {%8,%9}, {%0,%1,%2,%3};"
        : "+f"(d[0]), "+f"(d[1]), "+f"(d[2]), "+f"(d[3])
        : "r"(__float_as_uint(a[0])), "r"(__float_as_uint(a[1])),
          "r"(__float_as_uint(a[2])), "r"(__float_as_uint(a[3])),
          "r"(__float_as_uint(b[0])), "r"(__float_as_uint(b[1])));
}

// ============================================================
// QKV projection: Y[b,h,n,d] = X[row] @ W^T + bias, scattered head-major.
// ============================================================
__global__ __launch_bounds__(256) void proj_head_kernel(
    const float* __restrict__ X, const float* __restrict__ W,
    const float* __restrict__ bias, int sel)
{
    float* dst = sel == 0 ? g_qh : (sel == 1 ? g_kh : g_vh);
    __shared__ float As[128][36];
    __shared__ float Ws[64][36];
    int tid = threadIdx.x;
    int lane = tid & 31, warp = tid >> 5;
    int g = lane >> 2, t = lane & 3;
    int wm = warp >> 1, wn = warp & 1;
    int m0 = blockIdx.x * 128;
    int h  = blockIdx.y;

    float acc[2][4][4];
#pragma unroll
    for (int i = 0; i < 2; i++)
#pragma unroll
        for (int j = 0; j < 4; j++)
#pragma unroll
            for (int c = 0; c < 4; c++) acc[i][j][c] = 0.f;

    int rl = tid >> 3, cl = (tid & 7) * 4;
    for (int k0 = 0; k0 < DM; k0 += 32) {
#pragma unroll
        for (int i = 0; i < 4; i++) {
            int r = rl + i * 32;
            float4 v = *(const float4*)(X + (size_t)(m0 + r) * DM + k0 + cl);
            As[r][cl]   = to_tf32(v.x);
            As[r][cl+1] = to_tf32(v.y);
            As[r][cl+2] = to_tf32(v.z);
            As[r][cl+3] = to_tf32(v.w);
        }
#pragma unroll
        for (int i = 0; i < 2; i++) {
            int r = rl + i * 32;
            float4 v = *(const float4*)(W + (size_t)(h * 64 + r) * DM + k0 + cl);
            Ws[r][cl]   = to_tf32(v.x);
            Ws[r][cl+1] = to_tf32(v.y);
            Ws[r][cl+2] = to_tf32(v.z);
            Ws[r][cl+3] = to_tf32(v.w);
        }
        __syncthreads();
#pragma unroll
        for (int kk = 0; kk < 4; kk++) {
            float a[2][4];
#pragma unroll
            for (int mt = 0; mt < 2; mt++) {
                int rb = wm * 32 + mt * 16;
                a[mt][0] = As[rb + g][kk*8 + t];
                a[mt][1] = As[rb + 8 + g][kk*8 + t];
                a[mt][2] = As[rb + g][kk*8 + t + 4];
                a[mt][3] = As[rb + 8 + g][kk*8 + t + 4];
            }
            float bf[4][2];
#pragma unroll
            for (int nt = 0; nt < 4; nt++) {
                int nl = wn * 32 + nt * 8 + g;
                bf[nt][0] = Ws[nl][kk*8 + t];
                bf[nt][1] = Ws[nl][kk*8 + t + 4];
            }
#pragma unroll
            for (int mt = 0; mt < 2; mt++)
#pragma unroll
                for (int nt = 0; nt < 4; nt++)
                    mma8(acc[mt][nt], a[mt], bf[nt]);
        }
        __syncthreads();
    }
#pragma unroll
    for (int mt = 0; mt < 2; mt++) {
        int r0 = m0 + wm * 32 + mt * 16 + g;
        int r1 = r0 + 8;
#pragma unroll
        for (int nt = 0; nt < 4; nt++) {
            int col = wn * 32 + nt * 8 + 2 * t;
            float b0v = bias[h * 64 + col], b1v = bias[h * 64 + col + 1];
            int b_ = r0 >> 12, q_ = r0 & 4095;
            float* p = dst + (size_t)((b_ * HH + h) * NQ + q_) * DH + col;
            p[0] = acc[mt][nt][0] + b0v;
            p[1] = acc[mt][nt][1] + b1v;
            b_ = r1 >> 12; q_ = r1 & 4095;
            p = dst + (size_t)((b_ * HH + h) * NQ + q_) * DH + col;
            p[0] = acc[mt][nt][2] + b0v;
            p[1] = acc[mt][nt][3] + b1v;
        }
    }
}

// ============================================================
// Output projection: output = (concat_heads(g_o) * invZ) @ Wo^T + bo
// ============================================================
__global__ __launch_bounds__(256) void proj_out_kernel(
    const float* __restrict__ W, const float* __restrict__ bias,
    float* __restrict__ Y)
{
    __shared__ float As[128][36];
    __shared__ float Ws[64][36];
    int tid = threadIdx.x;
    int lane = tid & 31, warp = tid >> 5;
    int g = lane >> 2, t = lane & 3;
    int wm = warp >> 1, wn = warp & 1;
    int m0 = blockIdx.x * 128;
    int n0 = blockIdx.y * 64;

    float acc[2][4][4];
#pragma unroll
    for (int i = 0; i < 2; i++)
#pragma unroll
        for (int j = 0; j < 4; j++)
#pragma unroll
            for (int c = 0; c < 4; c++) acc[i][j][c] = 0.f;

    int rl = tid >> 3, cl = (tid & 7) * 4;
    for (int k0 = 0; k0 < DM; k0 += 32) {
        int head = k0 >> 6;
        int dd = (k0 & 63) + cl;
#pragma unroll
        for (int i = 0; i < 4; i++) {
            int r = rl + i * 32;
            int row = m0 + r;
            int b_ = row >> 12, q_ = row & 4095;
            size_t hb = (size_t)(b_ * HH + head) * NQ + q_;
            float zi = g_zi[hb];
            float4 v = *(const float4*)(g_o + hb * DH + dd);
            As[r][cl]   = to_tf32(v.x * zi);
            As[r][cl+1] = to_tf32(v.y * zi);
            As[r][cl+2] = to_tf32(v.z * zi);
            As[r][cl+3] = to_tf32(v.w * zi);
        }
#pragma unroll
        for (int i = 0; i < 2; i++) {
            int r = rl + i * 32;
            float4 v = *(const float4*)(W + (size_t)(n0 + r) * DM + k0 + cl);
            Ws[r][cl]   = to_tf32(v.x);
            Ws[r][cl+1] = to_tf32(v.y);
            Ws[r][cl+2] = to_tf32(v.z);
            Ws[r][cl+3] = to_tf32(v.w);
        }
        __syncthreads();
#pragma unroll
        for (int kk = 0; kk < 4; kk++) {
            float a[2][4];
#pragma unroll
            for (int mt = 0; mt < 2; mt++) {
                int rb = wm * 32 + mt * 16;
                a[mt][0] = As[rb + g][kk*8 + t];
                a[mt][1] = As[rb + 8 + g][kk*8 + t];
                a[mt][2] = As[rb + g][kk*8 + t + 4];
                a[mt][3] = As[rb + 8 + g][kk*8 + t + 4];
            }
            float bf[4][2];
#pragma unroll
            for (int nt = 0; nt < 4; nt++) {
                int nl = wn * 32 + nt * 8 + g;
                bf[nt][0] = Ws[nl][kk*8 + t];
                bf[nt][1] = Ws[nl][kk*8 + t + 4];
            }
#pragma unroll
            for (int mt = 0; mt < 2; mt++)
#pragma unroll
                for (int nt = 0; nt < 4; nt++)
                    mma8(acc[mt][nt], a[mt], bf[nt]);
        }
        __syncthreads();
    }
#pragma unroll
    for (int mt = 0; mt < 2; mt++) {
        int r0 = m0 + wm * 32 + mt * 16 + g;
        int r1 = r0 + 8;
#pragma unroll
        for (int nt = 0; nt < 4; nt++) {
            int col = wn * 32 + nt * 8 + 2 * t;
            float b0v = bias[n0 + col], b1v = bias[n0 + col + 1];
            float* p = Y + (size_t)r0 * DM + n0 + col;
            p[0] = acc[mt][nt][0] + b0v;
            p[1] = acc[mt][nt][1] + b1v;
            p = Y + (size_t)r1 * DM + n0 + col;
            p[0] = acc[mt][nt][2] + b0v;
            p[1] = acc[mt][nt][3] + b1v;
        }
    }
}

// ============================================================
// Attention (SINGLE PASS): per block = one (b,h) x one 64-row Q tile.
// Writes UNNORMALIZED E = exp(S) to attn, accumulates Z (stores 1/Z),
// accumulates unnormalized O = E @ V into g_o.
// Q mma fragments hoisted into registers for the whole loop.
// ============================================================
#define SM_Q 0
#define SM_K 4352
#define SM_V 13056
#define SM_P 21760
#define SM_Z 30208
#define SM_M 30272
#define SMEM_BYTES 129280

__global__ __launch_bounds__(256) void attn_kernel(
    const unsigned char* __restrict__ mask, float* __restrict__ attn)
{
    extern __shared__ float sm[];
    float* Qs = sm + SM_Q;                               // [64][68]
    float* Ks = sm + SM_K;                               // [128][68]
    float* Vs = sm + SM_V;                               // [128][68]
    float* Ps = sm + SM_P;                               // [64][132]
    float* Zs = sm + SM_Z;                               // [64]
    unsigned int* Ms = (unsigned int*)(sm + SM_M);       // [64][32] words

    int tid = threadIdx.x;
    int lane = tid & 31, warp = tid >> 5;
    int g = lane >> 2, t = lane & 3;
    int wm = warp >> 2;   // 0..1 : S row half
    int wn = warp & 3;    // 0..3 : S col quarter / O k-chunk
    int q0 = blockIdx.x * 64;
    int bh = blockIdx.y;
    int b = bh >> 3, h = bh & 7;
    size_t headbase = (size_t)(b * HH + h) * NQ * DH;
    const unsigned char* mbase = mask + (size_t)(b * NQ + q0) * NK;

    // load Q tile (pre-scaled by 1/sqrt(d)=1/8)
#pragma unroll
    for (int j = 0; j < 4; j++) {
        int idx = tid + j * 256;
        int r = idx >> 4, c = (idx & 15) * 4;
        float4 v = *(const float4*)(g_qh + headbase + (size_t)(q0 + r) * DH + c);
        Qs[r*68 + c]   = to_tf32(v.x * 0.125f);
        Qs[r*68 + c+1] = to_tf32(v.y * 0.125f);
        Qs[r*68 + c+2] = to_tf32(v.z * 0.125f);
        Qs[r*68 + c+3] = to_tf32(v.w * 0.125f);
    }
    if (tid < 64) Zs[tid] = 0.f;
    __syncthreads();

    // hoist Q fragments for the entire K loop: qa[mt][kk][4]
    float qa[2][8][4];
#pragma unroll
    for (int mt = 0; mt < 2; mt++) {
        int rb = wm * 32 + mt * 16;
#pragma unroll
        for (int kk = 0; kk < 8; kk++) {
            qa[mt][kk][0] = Qs[(rb + g) * 68 + kk*8 + t];
            qa[mt][kk][1] = Qs[(rb + 8 + g) * 68 + kk*8 + t];
            qa[mt][kk][2] = Qs[(rb + g) * 68 + kk*8 + t + 4];
            qa[mt][kk][3] = Qs[(rb + 8 + g) * 68 + kk*8 + t + 4];
        }
    }

    float oacc[2][8][4];
#pragma unroll
    for (int i = 0; i < 2; i++)
#pragma unroll
        for (int j = 0; j < 8; j++)
#pragma unroll
            for (int c = 0; c < 4; c++) oacc[i][j][c] = 0.f;

    for (int kt = 0; kt < NK / 128; kt++) {
        int k0 = kt * 128;
        __syncthreads();
#pragma unroll
        for (int j = 0; j < 8; j++) {
            int idx = tid + j * 256;
            int r = idx >> 4, c = (idx & 15) * 4;
            float4 v = *(const float4*)(g_kh + headbase + (size_t)(k0 + r) * DH + c);
            Ks[r*68 + c]   = to_tf32(v.x);
            Ks[r*68 + c+1] = to_tf32(v.y);
            Ks[r*68 + c+2] = to_tf32(v.z);
            Ks[r*68 + c+3] = to_tf32(v.w);
            float4 w = *(const float4*)(g_vh + headbase + (size_t)(k0 + r) * DH + c);
            Vs[r*68 + c]   = to_tf32(w.x);
            Vs[r*68 + c+1] = to_tf32(w.y);
            Vs[r*68 + c+2] = to_tf32(w.z);
            Vs[r*68 + c+3] = to_tf32(w.w);
        }
#pragma unroll
        for (int j = 0; j < 8; j++) {
            int idx = tid + j * 256;
            int r = idx >> 5, c = idx & 31;
            Ms[r * 32 + c] = *(const unsigned int*)(mbase + (size_t)r * NK + k0 + c * 4);
        }
        __syncthreads();

        // ---- S = Q K^T (tf32 mma, Q frags from registers) ----
        float sacc[2][4][4];
#pragma unroll
        for (int i = 0; i < 2; i++)
#pragma unroll
            for (int j = 0; j < 4; j++)
#pragma unroll
                for (int c = 0; c < 4; c++) sacc[i][j][c] = 0.f;
#pragma unroll
        for (int kk = 0; kk < 8; kk++) {
            float bf[4][2];
#pragma unroll
            for (int nt = 0; nt < 4; nt++) {
                int nl = wn * 32 + nt * 8 + g;
                bf[nt][0] = Ks[nl * 68 + kk*8 + t];
                bf[nt][1] = Ks[nl * 68 + kk*8 + t + 4];
            }
#pragma unroll
            for (int mt = 0; mt < 2; mt++)
#pragma unroll
                for (int nt = 0; nt < 4; nt++)
                    mma8(sacc[mt][nt], qa[mt][kk], bf[nt]);
        }

        // ---- E = exp(S) (masked), accumulate Z, stage to Ps ----
        const unsigned char* Mb = (const unsigned char*)Ms;
        float rsum[4] = {0.f, 0.f, 0.f, 0.f};
#pragma unroll
        for (int mt = 0; mt < 2; mt++) {
            int r0 = wm * 32 + mt * 16 + g, r1 = r0 + 8;
#pragma unroll
            for (int nt = 0; nt < 4; nt++) {
                int c0 = wn * 32 + nt * 8 + 2 * t;
                float p00 = Mb[r0*128 + c0]     ? 0.f : __expf(sacc[mt][nt][0]);
                float p01 = Mb[r0*128 + c0 + 1] ? 0.f : __expf(sacc[mt][nt][1]);
                float p10 = Mb[r1*128 + c0]     ? 0.f : __expf(sacc[mt][nt][2]);
                float p11 = Mb[r1*128 + c0 + 1] ? 0.f : __expf(sacc[mt][nt][3]);
                rsum[mt*2]     += p00 + p01;
                rsum[mt*2 + 1] += p10 + p11;
                Ps[r0*132 + c0]     = p00;
                Ps[r0*132 + c0 + 1] = p01;
                Ps[r1*132 + c0]     = p10;
                Ps[r1*132 + c0 + 1] = p11;
            }
        }
#pragma unroll
        for (int i = 0; i < 4; i++) {
            rsum[i] += __shfl_xor_sync(0xffffffffu, rsum[i], 1);
            rsum[i] += __shfl_xor_sync(0xffffffffu, rsum[i], 2);
        }
        if (t == 0) {
            atomicAdd(&Zs[wm*32 + g],      rsum[0]);
            atomicAdd(&Zs[wm*32 + 8 + g],  rsum[1]);
            atomicAdd(&Zs[wm*32 + 16 + g], rsum[2]);
            atomicAdd(&Zs[wm*32 + 24 + g], rsum[3]);
        }
        __syncthreads();

        // ---- write UNNORMALIZED E tile to gmem (attn layout [h*B+b, q, k]) ----
        size_t abase = ((size_t)(h * BB + b) * NQ + q0) * NK + k0;
#pragma unroll
        for (int j = 0; j < 8; j++) {
            int idx = tid + j * 256;
            int r = idx >> 5, c = (idx & 31) * 4;
            float4 v = *(const float4*)(Ps + r * 132 + c);
            *(float4*)(attn + abase + (size_t)r * NK + c) = v;
        }

        // ---- O += E @ V  (warp wn handles k-chunk wn*32..+32) ----
#pragma unroll
        for (int kk = 0; kk < 4; kk++) {
            int kb = wn * 32 + kk * 8;
            float a[2][4];
#pragma unroll
            for (int mt = 0; mt < 2; mt++) {
                int rb = wm * 32 + mt * 16;
                a[mt][0] = to_tf32(Ps[(rb + g) * 132 + kb + t]);
                a[mt][1] = to_tf32(Ps[(rb + 8 + g) * 132 + kb + t]);
                a[mt][2] = to_tf32(Ps[(rb + g) * 132 + kb + t + 4]);
                a[mt][3] = to_tf32(Ps[(rb + 8 + g) * 132 + kb + t + 4]);
            }
            float bf[8][2];
#pragma unroll
            for (int nt = 0; nt < 8; nt++) {
                bf[nt][0] = Vs[(kb + t) * 68 + nt * 8 + g];
                bf[nt][1] = Vs[(kb + t + 4) * 68 + nt * 8 + g];
            }
#pragma unroll
            for (int mt = 0; mt < 2; mt++)
#pragma unroll
                for (int nt = 0; nt < 8; nt++)
                    mma8(oacc[mt][nt], a[mt], bf[nt]);
        }
    }

    // ---- write 1/Z ----
    __syncthreads();
    if (tid < 64) {
        g_zi[(size_t)(b * HH + h) * NQ + q0 + tid] = 1.0f / Zs[tid];
    }

    // ---- reduce O across the 4 k-chunk warps via smem (reuse Ps) ----
    float* Os = Ps;
    for (int i = tid; i < 64 * 68; i += 256) Os[i] = 0.f;
    __syncthreads();
#pragma unroll
    for (int mt = 0; mt < 2; mt++) {
        int r0 = wm * 32 + mt * 16 + g, r1 = r0 + 8;
#pragma unroll
        for (int nt = 0; nt < 8; nt++) {
            int c0 = nt * 8 + 2 * t;
            atomicAdd(&Os[r0 * 68 + c0],     oacc[mt][nt][0]);
            atomicAdd(&Os[r0 * 68 + c0 + 1], oacc[mt][nt][1]);
            atomicAdd(&Os[r1 * 68 + c0],     oacc[mt][nt][2]);
            atomicAdd(&Os[r1 * 68 + c0 + 1], oacc[mt][nt][3]);
        }
    }
    __syncthreads();
#pragma unroll
    for (int j = 0; j < 4; j++) {
        int idx = tid + j * 256;
        int r = idx >> 4, c = (idx & 15) * 4;
        float4 v;
        v.x = Os[r * 68 + c];
        v.y = Os[r * 68 + c + 1];
        v.z = Os[r * 68 + c + 2];
        v.w = Os[r * 68 + c + 3];
        *(float4*)(g_o + headbase + (size_t)(q0 + r) * DH + c) = v;
    }
}

// ============================================================
// Normalize attn rows: attn[row, :] *= 1/Z  (pure DRAM streaming)
// attn row index a = (h*BB+b)*NQ + q ; g_zi index = (b*HH+h)*NQ + q
// ============================================================
__global__ __launch_bounds__(256) void norm_attn_kernel(float* __restrict__ attn)
{
    int a = blockIdx.x;                 // 0 .. 16*4096-1
    int hb = a >> 12;                   // h*BB + b
    int q  = a & 4095;
    int h = hb >> 1, b = hb & 1;
    float zi = g_zi[(size_t)(b * HH + h) * NQ + q];
    float4* row = (float4*)(attn + (size_t)a * NK);
    int i = threadIdx.x;
#pragma unroll
    for (int j = 0; j < 4; j++) {
        float4 v = row[i + j * 256];
        v.x *= zi; v.y *= zi; v.z *= zi; v.w *= zi;
        row[i + j * 256] = v;
    }
}

// ============================================================
extern "C" void kernel_launch(void* const* d_in, const int* in_sizes, int n_in,
                              void* d_out, int out_size)
{
    const float* q  = (const float*)d_in[0];
    const float* k  = (const float*)d_in[1];
    const float* v  = (const float*)d_in[2];
    const unsigned char* mask = (const unsigned char*)d_in[3];
    const float* Wq = (const float*)d_in[4];
    const float* bq = (const float*)d_in[5];
    const float* Wk = (const float*)d_in[6];
    const float* bk = (const float*)d_in[7];
    const float* Wv = (const float*)d_in[8];
    const float* bv = (const float*)d_in[9];
    const float* Wo = (const float*)d_in[10];
    const float* bo = (const float*)d_in[11];

    float* out  = (float*)d_out;
    float* attn = out;                                    // [16, 4096, 4096]
    float* outp = out + (size_t)HH * BB * NQ * NK;        // [2, 4096, 512]

    dim3 blk(256);
    proj_head_kernel<<<dim3(64, 8), blk>>>(q, Wq, bq, 0);
    proj_head_kernel<<<dim3(64, 8), blk>>>(k, Wk, bk, 1);
    proj_head_kernel<<<dim3(64, 8), blk>>>(v, Wv, bv, 2);

    cudaFuncSetAttribute(attn_kernel, cudaFuncAttributeMaxDynamicSharedMemorySize, SMEM_BYTES);
    attn_kernel<<<dim3(NQ / 64, BB * HH), blk, SMEM_BYTES>>>(mask, attn);

    norm_attn_kernel<<<dim3(HH * BB * NQ), blk>>>(attn);

    proj_out_kernel<<<dim3(64, 8), blk>>>(Wo, bo, outp);
}